// round 17
// baseline (speedup 1.0000x reference)
#include <cuda_runtime.h>
#include <cuda_bf16.h>
#include <cstdint>
#include <cstddef>

#define BB   4096
#define TT   32
#define HH   16
#define HSS  32
#define EE   512

// ---------------------------------------------------------------------------
// Scratch (__device__ globals; no dynamic allocation anywhere)
// Split-format tile arrays: [tile][ck 0..15][comp hi/lo][row 0..127][16 u32]
//   one u32 = two consecutive-k bf16 values; 16 slots carry 32 k-values with
//   the pair-permutation slot(p): g=p>>3,q=p&7 -> g*8 + 2*(q&3) + (q>>2)
// ---------------------------------------------------------------------------
__device__ float g_q[67108864];                         // [B][H][T][D]
__device__ float g_k[67108864];
__device__ float g_v[67108864];
__device__ __align__(16) uint32_t g_xs [67108864];      // x split   (1024 m-tiles)
__device__ __align__(16) uint32_t g_ots[67108864];      // attn out  (1024 m-tiles)
__device__ __align__(16) uint32_t g_wsp[1048576];       // weights   (16 tiles: q0-3,k0-3,v0-3,p0-3)

// ---------------------------------------------------------------------------
// helpers
// ---------------------------------------------------------------------------
__device__ __forceinline__ void split2(float x, float y,
                                       uint32_t& hi, uint32_t& lo) {
    __nv_bfloat16 hx = __float2bfloat16(x);
    __nv_bfloat16 hy = __float2bfloat16(y);
    float rx = x - __bfloat162float(hx);
    float ry = y - __bfloat162float(hy);
    __nv_bfloat16 lx = __float2bfloat16(rx);
    __nv_bfloat16 ly = __float2bfloat16(ry);
    hi = ((uint32_t)__bfloat16_as_ushort(hy) << 16) | __bfloat16_as_ushort(hx);
    lo = ((uint32_t)__bfloat16_as_ushort(ly) << 16) | __bfloat16_as_ushort(lx);
}

__device__ __forceinline__ void mma_bf16(float* c, const uint32_t* a, const uint32_t* b) {
    asm volatile(
        "mma.sync.aligned.m16n8k16.row.col.f32.bf16.bf16.f32 "
        "{%0,%1,%2,%3}, {%4,%5,%6,%7}, {%8,%9}, {%0,%1,%2,%3};"
        : "+f"(c[0]), "+f"(c[1]), "+f"(c[2]), "+f"(c[3])
        : "r"(a[0]), "r"(a[1]), "r"(a[2]), "r"(a[3]),
          "r"(b[0]), "r"(b[1]));
}

// split 16 consecutive fp32 (4 float4) into 8 hi/lo pair-words
__device__ __forceinline__ void split16(const float4* src, uint32_t* h, uint32_t* l) {
    float4 v0 = src[0], v1 = src[1], v2 = src[2], v3 = src[3];
    split2(v0.x, v0.y, h[0], l[0]); split2(v0.z, v0.w, h[1], l[1]);
    split2(v1.x, v1.y, h[2], l[2]); split2(v1.z, v1.w, h[3], l[3]);
    split2(v2.x, v2.y, h[4], l[4]); split2(v2.z, v2.w, h[5], l[5]);
    split2(v3.x, v3.y, h[6], l[6]); split2(v3.z, v3.w, h[7], l[7]);
}

// write 8 pair-words with slot permutation ({p0,p4,p1,p5},{p2,p6,p3,p7})
__device__ __forceinline__ void store_perm8(uint32_t* d, const uint32_t* p) {
    *(uint4*)(d)     = make_uint4(p[0], p[4], p[1], p[5]);
    *(uint4*)(d + 4) = make_uint4(p[2], p[6], p[3], p[7]);
}

// ---------------------------------------------------------------------------
// Pre-split converters
// ---------------------------------------------------------------------------
__global__ void __launch_bounds__(256)
convert_x_kernel(const float* __restrict__ x)
{
    const int mt = blockIdx.x, ck = blockIdx.y;
    const int tid = threadIdx.x, row = tid >> 1, half = tid & 1;
    uint32_t h[8], l[8];
    split16((const float4*)(x + ((size_t)(mt*128 + row))*EE + ck*32 + half*16), h, l);
    uint32_t* dh = g_xs + (((size_t)mt*16 + ck)*2)*2048 + row*16 + half*8;
    store_perm8(dh,        h);
    store_perm8(dh + 2048, l);
}

__global__ void __launch_bounds__(256)
convert_w_kernel(const float* __restrict__ Wq, const float* __restrict__ Wk,
                 const float* __restrict__ Wv, const float* __restrict__ Wp)
{
    const int wt = blockIdx.x, ck = blockIdx.y;
    const int arr = wt >> 2, nt = wt & 3;
    const float* W = (arr == 0) ? Wq : (arr == 1) ? Wk : (arr == 2) ? Wv : Wp;
    const int tid = threadIdx.x, row = tid >> 1, half = tid & 1;
    uint32_t h[8], l[8];
    split16((const float4*)(W + ((size_t)(nt*128 + row))*EE + ck*32 + half*16), h, l);
    uint32_t* dh = g_wsp + (((size_t)wt*16 + ck)*2)*2048 + row*16 + half*8;
    store_perm8(dh,        h);
    store_perm8(dh + 2048, l);
}

// ---------------------------------------------------------------------------
// GEMM machinery. CTA tile 128x128, K chunks of 32, 3-stage cp.async pipeline.
// smem stage: [A_hi|A_lo|B_hi|B_lo], each 128 rows x 24 u32 (16 data + 8 pad;
// stride 96B keeps the LDS.64 fragment loads conflict-free).
// ---------------------------------------------------------------------------
#define TILE_U32   3072                   // 128 * 24
#define STAGE_U32  (4*TILE_U32)           // 12288 u32 = 49152 B
#define STAGE_B    49152
#define SMEM_GEMM  (3*STAGE_B)            // 147456 B

__device__ __forceinline__ void cp_chunk(uint32_t sdst,
                                         const uint32_t* __restrict__ asrc,
                                         const uint32_t* __restrict__ bsrc,
                                         int tid) {
    const uint32_t* srcs[4] = { asrc, asrc + 2048, bsrc, bsrc + 2048 };
    #pragma unroll
    for (int c = 0; c < 4; c++) {
        #pragma unroll
        for (int i = 0; i < 2; i++) {
            int seg = tid * 2 + i;              // 512 segs of 16B per component
            int row = seg >> 2, s = seg & 3;
            uint32_t d = sdst + c*12288 + row*96 + s*16;
            const void* p = (const char*)srcs[c] + (size_t)seg*16;
            asm volatile("cp.async.cg.shared.global [%0], [%1], 16;"
                         :: "r"(d), "l"(p));
        }
    }
}

__device__ __forceinline__ void compute_chunk(const uint32_t* __restrict__ buf,
                                              int wm, int wn, int quad, int tq,
                                              float acc[4][4][4]) {
    const uint32_t* As_hi = buf;
    const uint32_t* As_lo = buf + TILE_U32;
    const uint32_t* Bs_hi = buf + 2*TILE_U32;
    const uint32_t* Bs_lo = buf + 3*TILE_U32;
    #pragma unroll
    for (int ks = 0; ks < 2; ks++) {
        const int col = ks * 8 + 2 * tq;
        uint32_t ah[4][4], al[4][4], bh[4][2], bl[4][2];
        #pragma unroll
        for (int mt = 0; mt < 4; mt++) {
            int r = (wm*64 + mt*16 + quad) * 24 + col;
            uint2 x0 = *(const uint2*)(As_hi + r);
            uint2 x1 = *(const uint2*)(As_hi + r + 8*24);
            ah[mt][0] = x0.x; ah[mt][1] = x1.x; ah[mt][2] = x0.y; ah[mt][3] = x1.y;
            uint2 y0 = *(const uint2*)(As_lo + r);
            uint2 y1 = *(const uint2*)(As_lo + r + 8*24);
            al[mt][0] = y0.x; al[mt][1] = y1.x; al[mt][2] = y0.y; al[mt][3] = y1.y;
        }
        #pragma unroll
        for (int nt = 0; nt < 4; nt++) {
            int rb = (wn*32 + nt*8 + quad) * 24 + col;
            uint2 b0 = *(const uint2*)(Bs_hi + rb);
            bh[nt][0] = b0.x; bh[nt][1] = b0.y;
            uint2 b1 = *(const uint2*)(Bs_lo + rb);
            bl[nt][0] = b1.x; bl[nt][1] = b1.y;
        }
        #pragma unroll
        for (int mt = 0; mt < 4; mt++)
            #pragma unroll
            for (int nt = 0; nt < 4; nt++) {
                mma_bf16(acc[mt][nt], ah[mt], bh[nt]);
                mma_bf16(acc[mt][nt], al[mt], bh[nt]);
                mma_bf16(acc[mt][nt], ah[mt], bl[nt]);
            }
    }
}

// atiles/btiles: per-tile split arrays, stride 4096 u32 per chunk (2 comps x 2048)
__device__ __forceinline__ void gemm_mainloop(const uint32_t* __restrict__ atiles,
                                              const uint32_t* __restrict__ btiles,
                                              uint32_t* smu, uint32_t smb, int tid,
                                              int wm, int wn, int quad, int tq,
                                              float acc[4][4][4]) {
    cp_chunk(smb + 0*STAGE_B, atiles,        btiles,        tid);
    asm volatile("cp.async.commit_group;" ::: "memory");
    cp_chunk(smb + 1*STAGE_B, atiles + 4096, btiles + 4096, tid);
    asm volatile("cp.async.commit_group;" ::: "memory");
    for (int ck = 0; ck < 16; ck++) {
        __syncthreads();                       // closes compute of stage (ck-1)%3
        if (ck + 2 < 16) {
            cp_chunk(smb + ((ck+2)%3)*STAGE_B,
                     atiles + (size_t)(ck+2)*4096, btiles + (size_t)(ck+2)*4096, tid);
            asm volatile("cp.async.commit_group;" ::: "memory");
            asm volatile("cp.async.wait_group 2;" ::: "memory");
        } else if (ck == 14) {
            asm volatile("cp.async.wait_group 1;" ::: "memory");
        } else {
            asm volatile("cp.async.wait_group 0;" ::: "memory");
        }
        __syncthreads();                       // copies visible to all warps
        compute_chunk(smu + (ck%3)*STAGE_U32, wm, wn, quad, tq, acc);
    }
}

// ---------------------------------------------------------------------------
// Kernel: QKV projection. grid(12, 1024): x = wtile (mat*4+ntile), y = M tile.
// ---------------------------------------------------------------------------
__global__ void __launch_bounds__(256, 1)
gemm_qkv_kernel()
{
    extern __shared__ uint32_t smu[];
    const uint32_t smb = (uint32_t)__cvta_generic_to_shared(smu);
    const int tid = threadIdx.x, warp = tid >> 5, lane = tid & 31;
    const int quad = lane >> 2, tq = lane & 3;
    const int wm = warp & 1, wn = warp >> 1;

    const int wti = blockIdx.x;               // 0..11
    const int mat = wti >> 2;
    const int n0  = (wti & 3) * 128;
    const int m0  = blockIdx.y * 128;

    float acc[4][4][4];
    #pragma unroll
    for (int i = 0; i < 4; i++)
        #pragma unroll
        for (int j = 0; j < 4; j++)
            #pragma unroll
            for (int k = 0; k < 4; k++) acc[i][j][k] = 0.f;

    gemm_mainloop(g_xs  + (size_t)blockIdx.y * 65536,
                  g_wsp + (size_t)wti        * 65536,
                  smu, smb, tid, wm, wn, quad, tq, acc);

    float* gout = (mat == 0) ? g_q : (mat == 1) ? g_k : g_v;
    #pragma unroll
    for (int mt = 0; mt < 4; mt++) {
        #pragma unroll
        for (int nt = 0; nt < 4; nt++) {
            const int n = n0 + wn * 32 + nt * 8 + 2 * tq;
            const int h = n >> 5, d = n & 31;
            #pragma unroll
            for (int rr = 0; rr < 2; rr++) {
                const int m = m0 + wm * 64 + mt * 16 + quad + rr * 8;
                const int b = m >> 5, t = m & 31;
                float2 v = make_float2(acc[mt][nt][rr*2], acc[mt][nt][rr*2+1]);
                *(float2*)(gout + (((size_t)b * HH + h) * TT + t) * HSS + d) = v;
            }
        }
    }
}

// ---------------------------------------------------------------------------
// Kernel: attention. one warp per (b,h); epilogue writes split format g_ots.
// ---------------------------------------------------------------------------
__global__ void __launch_bounds__(256, 1)
attn_kernel()
{
    extern __shared__ uint32_t smu[];
    float* smf = (float*)smu;
    const int tid = threadIdx.x, warp = tid >> 5, lane = tid & 31;
    const int g = blockIdx.x * 8 + warp;          // g = b*16 + h
    const int t = lane;
    float* ksm = smf + warp * 2304;               // 32 rows, stride 36
    float* vsm = ksm + 1152;

    const float* qb = g_q + (size_t)g * 1024;
    const float* kb = g_k + (size_t)g * 1024;
    const float* vb = g_v + (size_t)g * 1024;

    float q[32];
    #pragma unroll
    for (int j = 0; j < 8; j++) {
        float4 v = *(const float4*)(qb + t * 32 + j * 4);
        q[4*j] = v.x; q[4*j+1] = v.y; q[4*j+2] = v.z; q[4*j+3] = v.w;
        *(float4*)(ksm + t * 36 + j * 4) = *(const float4*)(kb + t * 32 + j * 4);
        *(float4*)(vsm + t * 36 + j * 4) = *(const float4*)(vb + t * 32 + j * 4);
    }
    __syncwarp();

    float r[32];
    #pragma unroll
    for (int s = 0; s < 32; s++) {
        float a = 0.f;
        #pragma unroll
        for (int j = 0; j < 8; j++) {
            float4 kv = *(const float4*)(ksm + s * 36 + j * 4);
            a += q[4*j]*kv.x + q[4*j+1]*kv.y + q[4*j+2]*kv.z + q[4*j+3]*kv.w;
        }
        r[s] = (s <= t) ? a * 0.17677669529663689f : -3.0e38f;
    }
    float mx = r[0];
    #pragma unroll
    for (int s = 1; s < 32; s++) mx = fmaxf(mx, r[s]);
    float sum = 0.f;
    #pragma unroll
    for (int s = 0; s < 32; s++) { r[s] = __expf(r[s] - mx); sum += r[s]; }
    const float inv = 1.f / sum;

    float o[32];
    #pragma unroll
    for (int j = 0; j < 32; j++) o[j] = 0.f;
    #pragma unroll
    for (int s = 0; s < 32; s++) {
        float w = r[s];
        #pragma unroll
        for (int j = 0; j < 8; j++) {
            float4 vv = *(const float4*)(vsm + s * 36 + j * 4);
            o[4*j] += w*vv.x; o[4*j+1] += w*vv.y; o[4*j+2] += w*vv.z; o[4*j+3] += w*vv.w;
        }
    }
    __syncwarp();
    #pragma unroll
    for (int j = 0; j < 32; j++) ksm[t * 33 + j] = o[j] * inv;   // transpose buf
    __syncwarp();

    // lane = d: gather column over t, split to bf16 pairs, write slot layout
    const int b = g >> 4, h = g & 15;
    const int mt = b >> 2, row = (b & 3) * 32 + lane;
    float col[32];
    #pragma unroll
    for (int tt = 0; tt < 32; tt++) col[tt] = ksm[tt * 33 + lane];
    uint32_t hh[16], ll[16];
    #pragma unroll
    for (int p = 0; p < 16; p++) split2(col[2*p], col[2*p+1], hh[p], ll[p]);

    uint32_t* dh = g_ots + (((size_t)mt*16 + h)*2)*2048 + row*16;
    uint32_t* dl = dh + 2048;
    *(uint4*)(dh)      = make_uint4(hh[0],  hh[4],  hh[1],  hh[5]);
    *(uint4*)(dh + 4)  = make_uint4(hh[2],  hh[6],  hh[3],  hh[7]);
    *(uint4*)(dh + 8)  = make_uint4(hh[8],  hh[12], hh[9],  hh[13]);
    *(uint4*)(dh + 12) = make_uint4(hh[10], hh[14], hh[11], hh[15]);
    *(uint4*)(dl)      = make_uint4(ll[0],  ll[4],  ll[1],  ll[5]);
    *(uint4*)(dl + 4)  = make_uint4(ll[2],  ll[6],  ll[3],  ll[7]);
    *(uint4*)(dl + 8)  = make_uint4(ll[8],  ll[12], ll[9],  ll[13]);
    *(uint4*)(dl + 12) = make_uint4(ll[10], ll[14], ll[11], ll[15]);
}

// ---------------------------------------------------------------------------
// Kernel: output projection + bias. grid(4, 1024): x = N tile, y = M tile.
// ---------------------------------------------------------------------------
__global__ void __launch_bounds__(256, 1)
gemm_proj_kernel(const float* __restrict__ bp, float* __restrict__ out)
{
    extern __shared__ uint32_t smu[];
    const uint32_t smb = (uint32_t)__cvta_generic_to_shared(smu);
    const int tid = threadIdx.x, warp = tid >> 5, lane = tid & 31;
    const int quad = lane >> 2, tq = lane & 3;
    const int wm = warp & 1, wn = warp >> 1;
    const int n0 = blockIdx.x * 128;
    const int m0 = blockIdx.y * 128;

    float acc[4][4][4];
    #pragma unroll
    for (int i = 0; i < 4; i++)
        #pragma unroll
        for (int j = 0; j < 4; j++)
            #pragma unroll
            for (int k = 0; k < 4; k++) acc[i][j][k] = 0.f;

    gemm_mainloop(g_ots + (size_t)blockIdx.y * 65536,
                  g_wsp + (size_t)(12 + blockIdx.x) * 65536,
                  smu, smb, tid, wm, wn, quad, tq, acc);

    #pragma unroll
    for (int mt = 0; mt < 4; mt++) {
        #pragma unroll
        for (int nt = 0; nt < 4; nt++) {
            const int n = n0 + wn * 32 + nt * 8 + 2 * tq;
            const float b0 = bp[n], b1 = bp[n + 1];
            #pragma unroll
            for (int rr = 0; rr < 2; rr++) {
                const int m = m0 + wm * 64 + mt * 16 + quad + rr * 8;
                float2 v = make_float2(acc[mt][nt][rr*2] + b0,
                                       acc[mt][nt][rr*2+1] + b1);
                *(float2*)(out + (size_t)m * EE + n) = v;
            }
        }
    }
}

// ---------------------------------------------------------------------------
// Launch
// ---------------------------------------------------------------------------
extern "C" void kernel_launch(void* const* d_in, const int* in_sizes, int n_in,
                              void* d_out, int out_size)
{
    const float* x  = (const float*)d_in[0];
    const float* Wq = (const float*)d_in[1];
    const float* Wk = (const float*)d_in[2];
    const float* Wv = (const float*)d_in[3];
    const float* Wp = (const float*)d_in[4];
    const float* bp = (const float*)d_in[5];
    float* out = (float*)d_out;

    const int smem_attn = 8 * 2304 * 4;   // 73728

    cudaFuncSetAttribute(gemm_qkv_kernel,  cudaFuncAttributeMaxDynamicSharedMemorySize, SMEM_GEMM);
    cudaFuncSetAttribute(gemm_proj_kernel, cudaFuncAttributeMaxDynamicSharedMemorySize, SMEM_GEMM);
    cudaFuncSetAttribute(attn_kernel,      cudaFuncAttributeMaxDynamicSharedMemorySize, smem_attn);

    convert_x_kernel<<<dim3(1024, 16), 256>>>(x);
    convert_w_kernel<<<dim3(16, 16), 256>>>(Wq, Wk, Wv, Wp);
    gemm_qkv_kernel<<<dim3(12, 1024), 256, SMEM_GEMM>>>();
    attn_kernel<<<(BB * HH) / 8, 256, smem_attn>>>();
    gemm_proj_kernel<<<dim3(4, 1024), 256, SMEM_GEMM>>>(bp, out);
}